// round 1
// baseline (speedup 1.0000x reference)
#include <cuda_runtime.h>
#include <math.h>

// ----- problem constants -----
#define BB    2
#define AA    900
#define EDD   256
#define NGRP  8
#define NCAM  6
#define NLVL  4
#define NPT   7
#define NW    1344          // NGRP*NCAM*NLVL*NPT
#define NBA   (BB*AA)       // 1800
#define TILE_A 15           // 900 % 15 == 0

// ----- scratch (allocation-free: device globals) -----
__device__ float g_w[NBA * NW];                 // fc logits -> softmax weights (9.7 MB)
__device__ float g_grid[NBA * NCAM * NPT * 2];  // normalized grid coords
__device__ float g_fused[NBA * EDD];            // fused features before out-proj

// =====================================================================
// Kernel 1: FC  w = (inst + emb) @ w_fc^T + b_fc   -> g_w (raw logits)
// Block: 224 threads, covers TILE_A=15 anchors; each thread -> 6 outputs.
// =====================================================================
__global__ void __launch_bounds__(224) fc_kernel(
    const float* __restrict__ inst, const float* __restrict__ emb,
    const float* __restrict__ w_fc, const float* __restrict__ b_fc)
{
    __shared__ float s_feat[TILE_A][EDD];
    const int bx  = blockIdx.x;                 // 0..119
    const int b   = bx / (AA / TILE_A);
    const int a0  = (bx % (AA / TILE_A)) * TILE_A;
    const int tid = threadIdx.x;                // 0..223

    for (int i = tid; i < TILE_A * EDD; i += 224) {
        int a = i / EDD, k = i % EDD;
        size_t off = ((size_t)(b * AA + a0 + a)) * EDD + k;
        s_feat[a][k] = inst[off] + emb[off];
    }
    __syncthreads();

    float acc[6][TILE_A];
#pragma unroll
    for (int i = 0; i < 6; i++)
#pragma unroll
        for (int a = 0; a < TILE_A; a++) acc[i][a] = 0.f;

    for (int k = 0; k < EDD; k++) {
        float fv[TILE_A];
#pragma unroll
        for (int a = 0; a < TILE_A; a++) fv[a] = s_feat[a][k];  // smem broadcast
#pragma unroll
        for (int i = 0; i < 6; i++) {
            float wv = w_fc[(size_t)(tid + i * 224) * EDD + k];
#pragma unroll
            for (int a = 0; a < TILE_A; a++) acc[i][a] = fmaf(wv, fv[a], acc[i][a]);
        }
    }

#pragma unroll
    for (int i = 0; i < 6; i++) {
        int o = tid + i * 224;
        float bb = b_fc[o];
        for (int a = 0; a < TILE_A; a++)
            g_w[((size_t)(b * AA + a0 + a)) * NW + o] = acc[i][a] + bb;
    }
}

// =====================================================================
// Kernel 2: softmax over the 168 (cam,lvl,pt) entries per group, in place.
// Block per anchor; warp g handles group g (stride-8 elements).
// =====================================================================
__global__ void __launch_bounds__(256) softmax_kernel()
{
    __shared__ float s[NW];
    const int ba = blockIdx.x;
    float* wp = g_w + (size_t)ba * NW;
    for (int i = threadIdx.x; i < NW; i += 256) s[i] = wp[i];
    __syncthreads();

    const int g = threadIdx.x >> 5, lane = threadIdx.x & 31;
    float m = -INFINITY;
    for (int c = lane; c < 168; c += 32) m = fmaxf(m, s[c * 8 + g]);
#pragma unroll
    for (int o = 16; o; o >>= 1) m = fmaxf(m, __shfl_xor_sync(0xffffffffu, m, o));
    float sum = 0.f;
    for (int c = lane; c < 168; c += 32) {
        float e = expf(s[c * 8 + g] - m);
        s[c * 8 + g] = e;
        sum += e;
    }
#pragma unroll
    for (int o = 16; o; o >>= 1) sum += __shfl_xor_sync(0xffffffffu, sum, o);
    float inv = 1.f / sum;
    for (int c = lane; c < 168; c += 32) wp[c * 8 + g] = s[c * 8 + g] * inv;
}

// =====================================================================
// Kernel 3: keypoints + projection -> normalized grid coords
// one thread per (b,a,cam,p)
// =====================================================================
__global__ void grid_kernel(const float* __restrict__ anchor,
                            const float* __restrict__ proj,
                            const float* __restrict__ wh)
{
    const float fsx[7] = {0.f, 0.45f, -0.45f, 0.f,   0.f,   0.f,   0.f};
    const float fsy[7] = {0.f, 0.f,    0.f,   0.45f, -0.45f, 0.f,  0.f};
    const float fsz[7] = {0.f, 0.f,    0.f,   0.f,   0.f,   0.45f, -0.45f};

    int idx = blockIdx.x * blockDim.x + threadIdx.x;
    const int total = NBA * NCAM * NPT;
    if (idx >= total) return;
    int p = idx % NPT;
    int t = idx / NPT;
    int cam = t % NCAM;
    int ba = t / NCAM;                 // b*AA + a
    int b = ba / AA;

    const float* an = anchor + (size_t)ba * 8;
    float e0 = expf(an[3]), e1 = expf(an[4]), e2 = expf(an[5]);
    float k0 = fsx[p] * e0, k1 = fsy[p] * e1, k2 = fsz[p] * e2;
    float sn = an[6], cs = an[7];
    float X = cs * k0 - sn * k1 + an[0];
    float Y = sn * k0 + cs * k1 + an[1];
    float Z = k2 + an[2];

    const float* M = proj + (size_t)(b * NCAM + cam) * 16;
    float d0 = M[0] * X + M[1] * Y + M[2]  * Z + M[3];
    float d1 = M[4] * X + M[5] * Y + M[6]  * Z + M[7];
    float d2 = M[8] * X + M[9] * Y + M[10] * Z + M[11];
    float iz = 1.f / fmaxf(d2, 1e-5f);
    float x = d0 * iz, y = d1 * iz;
    x /= fmaxf(wh[(size_t)(b * NCAM + cam) * 2 + 0], 1e-5f);
    y /= fmaxf(wh[(size_t)(b * NCAM + cam) * 2 + 1], 1e-5f);

    size_t go = ((size_t)(ba * NCAM + cam) * NPT + p) * 2;
    g_grid[go + 0] = x * 2.f - 1.f;
    g_grid[go + 1] = y * 2.f - 1.f;
}

// =====================================================================
// Kernel 4: bilinear sampling + weighted fusion -> g_fused
// Block per anchor, 256 threads (one per channel c; group g = c>>5).
// =====================================================================
__global__ void __launch_bounds__(256) agg_kernel(
    const float* __restrict__ f0, const float* __restrict__ f1,
    const float* __restrict__ f2, const float* __restrict__ f3)
{
    __shared__ float s_w[NW];
    __shared__ float s_grid[NCAM * NPT * 2];

    const int ba = blockIdx.x;
    const int b  = ba / AA;
    const int c  = threadIdx.x;
    const int g  = c >> 5;

    for (int i = c; i < NW; i += 256) s_w[i] = g_w[(size_t)ba * NW + i];
    if (c < NCAM * NPT * 2) s_grid[c] = g_grid[(size_t)ba * (NCAM * NPT * 2) + c];
    __syncthreads();

    const float* fl[4] = {f0, f1, f2, f3};
    const int Hl[4] = {64, 32, 16, 8};
    const int Wl[4] = {176, 88, 44, 22};

    float acc = 0.f;
    for (int cam = 0; cam < NCAM; cam++) {
        for (int p = 0; p < NPT; p++) {
            float u = s_grid[(cam * NPT + p) * 2 + 0];
            float v = s_grid[(cam * NPT + p) * 2 + 1];
#pragma unroll
            for (int lvl = 0; lvl < NLVL; lvl++) {
                const int H = Hl[lvl], W = Wl[lvl];
                float gx = (u + 1.f) * (W * 0.5f) - 0.5f;
                float gy = (v + 1.f) * (H * 0.5f) - 0.5f;
                float x0f = floorf(gx), y0f = floorf(gy);
                float wx1 = gx - x0f, wy1 = gy - y0f;
                bool vx0 = (x0f >= 0.f)       && (x0f <= (float)(W - 1));
                bool vx1 = (x0f + 1.f >= 0.f) && (x0f + 1.f <= (float)(W - 1));
                bool vy0 = (y0f >= 0.f)       && (y0f <= (float)(H - 1));
                bool vy1 = (y0f + 1.f >= 0.f) && (y0f + 1.f <= (float)(H - 1));
                if (!((vx0 || vx1) && (vy0 || vy1))) continue;

                int x0 = (int)fminf(fmaxf(x0f, 0.f),       (float)(W - 1));
                int x1 = (int)fminf(fmaxf(x0f + 1.f, 0.f), (float)(W - 1));
                int y0 = (int)fminf(fmaxf(y0f, 0.f),       (float)(H - 1));
                int y1 = (int)fminf(fmaxf(y0f + 1.f, 0.f), (float)(H - 1));

                const float* base = fl[lvl] +
                    ((size_t)((b * NCAM + cam) * EDD + c)) * (size_t)(H * W);
                float s = 0.f;
                if (vx0 && vy0) s = fmaf((1.f - wx1) * (1.f - wy1), base[y0 * W + x0], s);
                if (vx1 && vy0) s = fmaf(wx1 * (1.f - wy1),         base[y0 * W + x1], s);
                if (vx0 && vy1) s = fmaf((1.f - wx1) * wy1,         base[y1 * W + x0], s);
                if (vx1 && vy1) s = fmaf(wx1 * wy1,                 base[y1 * W + x1], s);

                acc = fmaf(s, s_w[((cam * NLVL + lvl) * NPT + p) * 8 + g], acc);
            }
        }
    }
    g_fused[(size_t)ba * EDD + c] = acc;
}

// =====================================================================
// Kernel 5: out = fused @ w_out^T + b_out
// Block: 256 threads (one output each), TILE_A=15 anchors per block.
// =====================================================================
__global__ void __launch_bounds__(256) outproj_kernel(
    const float* __restrict__ w_out, const float* __restrict__ b_out,
    float* __restrict__ out)
{
    __shared__ float s_f[TILE_A][EDD];
    const int bx = blockIdx.x;                  // 0..119
    const int b  = bx / (AA / TILE_A);
    const int a0 = (bx % (AA / TILE_A)) * TILE_A;
    const int j  = threadIdx.x;

    for (int i = j; i < TILE_A * EDD; i += 256) {
        int a = i / EDD, k = i % EDD;
        s_f[a][k] = g_fused[((size_t)(b * AA + a0 + a)) * EDD + k];
    }
    __syncthreads();

    float acc[TILE_A];
#pragma unroll
    for (int a = 0; a < TILE_A; a++) acc[a] = 0.f;
    const float* wr = w_out + (size_t)j * EDD;
    for (int k = 0; k < EDD; k++) {
        float wv = wr[k];
#pragma unroll
        for (int a = 0; a < TILE_A; a++) acc[a] = fmaf(wv, s_f[a][k], acc[a]);
    }
    float bb = b_out[j];
#pragma unroll
    for (int a = 0; a < TILE_A; a++)
        out[((size_t)(b * AA + a0 + a)) * EDD + j] = acc[a] + bb;
}

// =====================================================================
// launch
// =====================================================================
extern "C" void kernel_launch(void* const* d_in, const int* in_sizes, int n_in,
                              void* d_out, int out_size)
{
    const float* inst   = (const float*)d_in[0];
    const float* anchor = (const float*)d_in[1];
    const float* emb    = (const float*)d_in[2];
    const float* f0     = (const float*)d_in[3];
    const float* f1     = (const float*)d_in[4];
    const float* f2     = (const float*)d_in[5];
    const float* f3     = (const float*)d_in[6];
    const float* proj   = (const float*)d_in[7];
    const float* wh     = (const float*)d_in[8];
    const float* w_fc   = (const float*)d_in[9];
    const float* b_fc   = (const float*)d_in[10];
    const float* w_out  = (const float*)d_in[11];
    const float* b_out  = (const float*)d_in[12];
    float* out = (float*)d_out;

    fc_kernel<<<(AA / TILE_A) * BB, 224>>>(inst, emb, w_fc, b_fc);
    softmax_kernel<<<NBA, 256>>>();
    {
        int total = NBA * NCAM * NPT;
        grid_kernel<<<(total + 255) / 256, 256>>>(anchor, proj, wh);
    }
    agg_kernel<<<NBA, 256>>>(f0, f1, f2, f3);
    outproj_kernel<<<(AA / TILE_A) * BB, 256>>>(w_out, b_out, out);
}

// round 2
// speedup vs baseline: 2.0720x; 2.0720x over previous
#include <cuda_runtime.h>
#include <math.h>

// ----- problem constants -----
#define BB    2
#define AA    900
#define EDD   256
#define NGRP  8
#define NCAM  6
#define NLVL  4
#define NPT   7
#define NW    1344          // NGRP*NCAM*NLVL*NPT
#define NBA   (BB*AA)       // 1800
#define NDESC (NCAM*NPT*NLVL) // 168

// ----- scratch (allocation-free: device globals) -----
__device__ float g_w[NBA * NW];       // fc logits (softmax applied inside agg)
__device__ float g_fused[NBA * EDD];  // fused features before out-proj

// =====================================================================
// Tiled SGEMM: C[M,N] = A[M,K=256] (+A2) @ B[N,K=256]^T (+bias)
// 64x64 tile, BK=32, 128 threads, 8x4 micro-tile per thread.
// =====================================================================
template<int N_DIM, bool ADD2, bool BIAS>
__global__ void __launch_bounds__(128) sgemm_kernel(
    const float* __restrict__ A, const float* __restrict__ A2,
    const float* __restrict__ Bw, const float* __restrict__ bias,
    float* __restrict__ C, int M)
{
    __shared__ float As[32][64];
    __shared__ float Bs[32][64];
    const int bm0 = blockIdx.y * 64;
    const int bn0 = blockIdx.x * 64;
    const int tid = threadIdx.x;
    const int tx = tid & 15;       // n dir (16 * 4 = 64)
    const int ty = tid >> 4;       // m dir (8 * 8 = 64)

    float acc[8][4];
#pragma unroll
    for (int i = 0; i < 8; i++)
#pragma unroll
        for (int j = 0; j < 4; j++) acc[i][j] = 0.f;

    for (int kt = 0; kt < 256; kt += 32) {
#pragma unroll
        for (int s = 0; s < 4; s++) {
            int id  = tid + s * 128;       // 0..511
            int row = id >> 3;             // 0..63
            int ch  = id & 7;              // 0..7 (float4 chunk)
            // ---- A tile (guarded on M) ----
            int m = bm0 + row;
            float4 v = make_float4(0.f, 0.f, 0.f, 0.f);
            if (m < M) {
                v = *(const float4*)(A + (size_t)m * 256 + kt + ch * 4);
                if (ADD2) {
                    float4 w2 = *(const float4*)(A2 + (size_t)m * 256 + kt + ch * 4);
                    v.x += w2.x; v.y += w2.y; v.z += w2.z; v.w += w2.w;
                }
            }
            As[ch * 4 + 0][row] = v.x;
            As[ch * 4 + 1][row] = v.y;
            As[ch * 4 + 2][row] = v.z;
            As[ch * 4 + 3][row] = v.w;
            // ---- B tile (N divisible by 64, no guard) ----
            int n = bn0 + row;
            float4 u = *(const float4*)(Bw + (size_t)n * 256 + kt + ch * 4);
            Bs[ch * 4 + 0][row] = u.x;
            Bs[ch * 4 + 1][row] = u.y;
            Bs[ch * 4 + 2][row] = u.z;
            Bs[ch * 4 + 3][row] = u.w;
        }
        __syncthreads();

#pragma unroll 8
        for (int k = 0; k < 32; k++) {
            float4 a0 = *(const float4*)&As[k][ty * 8];
            float4 a1 = *(const float4*)&As[k][ty * 8 + 4];
            float4 bv = *(const float4*)&Bs[k][tx * 4];
            float am[8] = {a0.x, a0.y, a0.z, a0.w, a1.x, a1.y, a1.z, a1.w};
            float bn4[4] = {bv.x, bv.y, bv.z, bv.w};
#pragma unroll
            for (int i = 0; i < 8; i++)
#pragma unroll
                for (int j = 0; j < 4; j++)
                    acc[i][j] = fmaf(am[i], bn4[j], acc[i][j]);
        }
        __syncthreads();
    }

    int n0 = bn0 + tx * 4;
    float4 bb = make_float4(0.f, 0.f, 0.f, 0.f);
    if (BIAS) bb = *(const float4*)(bias + n0);
#pragma unroll
    for (int i = 0; i < 8; i++) {
        int m = bm0 + ty * 8 + i;
        if (m >= M) continue;
        float4 o;
        o.x = acc[i][0] + bb.x;
        o.y = acc[i][1] + bb.y;
        o.z = acc[i][2] + bb.z;
        o.w = acc[i][3] + bb.w;
        *(float4*)(C + (size_t)m * N_DIM + n0) = o;
    }
}

// =====================================================================
// Fused aggregation: softmax + keypoint projection + descriptor
// precompute + valid-sample compaction + gather/fuse.
// One block per anchor, 256 threads (one channel each).
// =====================================================================
__global__ void __launch_bounds__(256) agg_kernel(
    const float* __restrict__ f0, const float* __restrict__ f1,
    const float* __restrict__ f2, const float* __restrict__ f3,
    const float* __restrict__ anchor, const float* __restrict__ proj,
    const float* __restrict__ wh)
{
    __shared__ float  s_w[NW];
    __shared__ float  s_uv[NCAM * NPT][2];
    __shared__ int    s_foff[NDESC];
    __shared__ int    s_dx[NDESC];
    __shared__ int    s_dyW[NDESC];
    __shared__ float4 s_wt[NDESC];
    __shared__ int    s_widx[NDESC];
    __shared__ int    s_list[NDESC];
    __shared__ int    s_wcnt[8];

    const int ba   = blockIdx.x;
    const int b    = ba / AA;
    const int tid  = threadIdx.x;
    const int c    = tid;
    const int wrp  = tid >> 5;
    const int lane = tid & 31;

    // ---- load raw logits ----
    for (int i = tid; i < NW; i += 256) s_w[i] = g_w[(size_t)ba * NW + i];

    // ---- projection of 42 (cam,pt) keypoints ----
    if (tid < NCAM * NPT) {
        const float fsx[7] = {0.f, 0.45f, -0.45f, 0.f, 0.f, 0.f, 0.f};
        const float fsy[7] = {0.f, 0.f, 0.f, 0.45f, -0.45f, 0.f, 0.f};
        const float fsz[7] = {0.f, 0.f, 0.f, 0.f, 0.f, 0.45f, -0.45f};
        int cam = tid / NPT, p = tid % NPT;
        const float* an = anchor + (size_t)ba * 8;
        float e0 = expf(an[3]), e1 = expf(an[4]), e2 = expf(an[5]);
        float k0 = fsx[p] * e0, k1 = fsy[p] * e1, k2 = fsz[p] * e2;
        float sn = an[6], cs = an[7];
        float X = cs * k0 - sn * k1 + an[0];
        float Y = sn * k0 + cs * k1 + an[1];
        float Z = k2 + an[2];
        const float* M = proj + (size_t)(b * NCAM + cam) * 16;
        float d0 = M[0] * X + M[1] * Y + M[2]  * Z + M[3];
        float d1 = M[4] * X + M[5] * Y + M[6]  * Z + M[7];
        float d2 = M[8] * X + M[9] * Y + M[10] * Z + M[11];
        float iz = 1.f / fmaxf(d2, 1e-5f);
        float x = d0 * iz / fmaxf(wh[(size_t)(b * NCAM + cam) * 2 + 0], 1e-5f);
        float y = d1 * iz / fmaxf(wh[(size_t)(b * NCAM + cam) * 2 + 1], 1e-5f);
        s_uv[tid][0] = x * 2.f - 1.f;
        s_uv[tid][1] = y * 2.f - 1.f;
    }
    __syncthreads();

    // ---- softmax over 168 entries for group = warp id (warp-local data) ----
    {
        float mx = -INFINITY;
        for (int cc = lane; cc < 168; cc += 32) mx = fmaxf(mx, s_w[cc * 8 + wrp]);
#pragma unroll
        for (int o = 16; o; o >>= 1) mx = fmaxf(mx, __shfl_xor_sync(0xffffffffu, mx, o));
        float sum = 0.f;
        for (int cc = lane; cc < 168; cc += 32) {
            float e = expf(s_w[cc * 8 + wrp] - mx);
            s_w[cc * 8 + wrp] = e;
            sum += e;
        }
#pragma unroll
        for (int o = 16; o; o >>= 1) sum += __shfl_xor_sync(0xffffffffu, sum, o);
        float inv = 1.f / sum;
        for (int cc = lane; cc < 168; cc += 32) s_w[cc * 8 + wrp] *= inv;
    }

    // ---- descriptor precompute for 168 (cam,pt,lvl) samples ----
    const int Hl[4]  = {64, 32, 16, 8};
    const int Wl[4]  = {176, 88, 44, 22};
    const int HWl[4] = {11264, 2816, 704, 176};
    int flag = 0;
    if (tid < NDESC) {
        int d = tid;
        int cam = d / (NPT * NLVL);
        int r   = d - cam * (NPT * NLVL);
        int p   = r >> 2;
        int lvl = r & 3;
        float u = s_uv[cam * NPT + p][0];
        float v = s_uv[cam * NPT + p][1];
        const int H = Hl[lvl], W = Wl[lvl];
        float gx = (u + 1.f) * (W * 0.5f) - 0.5f;
        float gy = (v + 1.f) * (H * 0.5f) - 0.5f;
        float x0f = floorf(gx), y0f = floorf(gy);
        float wx1 = gx - x0f, wy1 = gy - y0f;
        bool vx0 = (x0f >= 0.f)       && (x0f <= (float)(W - 1));
        bool vx1 = (x0f + 1.f >= 0.f) && (x0f + 1.f <= (float)(W - 1));
        bool vy0 = (y0f >= 0.f)       && (y0f <= (float)(H - 1));
        bool vy1 = (y0f + 1.f >= 0.f) && (y0f + 1.f <= (float)(H - 1));
        flag = ((vx0 || vx1) && (vy0 || vy1)) ? 1 : 0;
        int x0 = (int)fminf(fmaxf(x0f, 0.f),       (float)(W - 1));
        int x1 = (int)fminf(fmaxf(x0f + 1.f, 0.f), (float)(W - 1));
        int y0 = (int)fminf(fmaxf(y0f, 0.f),       (float)(H - 1));
        int y1 = (int)fminf(fmaxf(y0f + 1.f, 0.f), (float)(H - 1));
        s_foff[d] = (b * NCAM + cam) * EDD * HWl[lvl] + y0 * W + x0;
        s_dx[d]   = x1 - x0;
        s_dyW[d]  = (y1 - y0) * W;
        float4 wt;
        wt.x = (vx0 && vy0) ? (1.f - wx1) * (1.f - wy1) : 0.f;
        wt.y = (vx1 && vy0) ? wx1 * (1.f - wy1)         : 0.f;
        wt.z = (vx0 && vy1) ? (1.f - wx1) * wy1         : 0.f;
        wt.w = (vx1 && vy1) ? wx1 * wy1                 : 0.f;
        s_wt[d]   = wt;
        s_widx[d] = ((cam * NLVL + lvl) * NPT + p) * NGRP;
    }

    // ---- deterministic compaction of valid descriptors (warp ballots) ----
    unsigned bal = 0;
    if (wrp < 6) {
        bal = __ballot_sync(0xffffffffu, flag);
        if (lane == 0) s_wcnt[wrp] = __popc(bal);
    } else {
        if (lane == 0) s_wcnt[wrp] = 0;
    }
    __syncthreads();
    if (wrp < 6 && flag) {
        int base = 0;
        for (int w2 = 0; w2 < wrp; w2++) base += s_wcnt[w2];
        int pos = base + __popc(bal & ((1u << lane) - 1u));
        s_list[pos] = tid;
    }
    __syncthreads();
    int cnt = s_wcnt[0] + s_wcnt[1] + s_wcnt[2] + s_wcnt[3] + s_wcnt[4] + s_wcnt[5];

    // ---- gather + fuse over valid samples only ----
    const int c0 = c * 11264, c1 = c * 2816, c2 = c * 704, c3 = c * 176;
    const int g = wrp;
    float acc = 0.f;
    for (int i = 0; i < cnt; i++) {
        int d   = s_list[i];
        int lvl = d & 3;
        const float* fp = (lvl == 0) ? f0 : (lvl == 1) ? f1 : (lvl == 2) ? f2 : f3;
        int coff        = (lvl == 0) ? c0 : (lvl == 1) ? c1 : (lvl == 2) ? c2 : c3;
        const float* basep = fp + (size_t)(s_foff[d] + coff);
        int dx = s_dx[d], dyW = s_dyW[d];
        float4 wt = s_wt[d];
        float v00 = basep[0];
        float v01 = basep[dx];
        float v10 = basep[dyW];
        float v11 = basep[dyW + dx];
        float s = fmaf(wt.x, v00, fmaf(wt.y, v01, fmaf(wt.z, v10, wt.w * v11)));
        acc = fmaf(s, s_w[s_widx[d] + g], acc);
    }
    g_fused[(size_t)ba * EDD + c] = acc;
}

// =====================================================================
// launch
// =====================================================================
extern "C" void kernel_launch(void* const* d_in, const int* in_sizes, int n_in,
                              void* d_out, int out_size)
{
    const float* inst   = (const float*)d_in[0];
    const float* anchor = (const float*)d_in[1];
    const float* emb    = (const float*)d_in[2];
    const float* f0     = (const float*)d_in[3];
    const float* f1     = (const float*)d_in[4];
    const float* f2     = (const float*)d_in[5];
    const float* f3     = (const float*)d_in[6];
    const float* proj   = (const float*)d_in[7];
    const float* wh     = (const float*)d_in[8];
    const float* w_fc   = (const float*)d_in[9];
    const float* b_fc   = (const float*)d_in[10];
    const float* w_out  = (const float*)d_in[11];
    const float* b_out  = (const float*)d_in[12];
    float* out = (float*)d_out;

    float* gw_ptr;
    float* gf_ptr;
    cudaGetSymbolAddress((void**)&gw_ptr, g_w);
    cudaGetSymbolAddress((void**)&gf_ptr, g_fused);

    // FC: [1800,256] @ [1344,256]^T + b_fc -> g_w
    {
        dim3 grid(NW / 64, (NBA + 63) / 64);
        sgemm_kernel<NW, true, true><<<grid, 128>>>(inst, emb, w_fc, b_fc, gw_ptr, NBA);
    }
    // fused softmax + projection + sampling + fusion
    agg_kernel<<<NBA, 256>>>(f0, f1, f2, f3, anchor, proj, wh);
    // out-projection: [1800,256] @ [256,256]^T + b_out -> out
    {
        dim3 grid(EDD / 64, (NBA + 63) / 64);
        sgemm_kernel<EDD, false, true><<<grid, 128>>>(gf_ptr, (const float*)0, w_out, b_out, out, NBA);
    }
}

// round 3
// speedup vs baseline: 2.0872x; 1.0074x over previous
#include <cuda_runtime.h>
#include <math.h>

// ----- problem constants -----
#define BB    2
#define AA    900
#define EDD   256
#define NGRP  8
#define NCAM  6
#define NLVL  4
#define NPT   7
#define NW    1344            // NGRP*NCAM*NLVL*NPT
#define NBA   (BB*AA)         // 1800
#define NDESC (NCAM*NPT*NLVL) // 168

// ----- scratch (allocation-free: device globals) -----
__device__ float g_featT[EDD * NBA];   // (inst+emb)^T   [256][1800]
__device__ float g_wfcT[EDD * NW];     // w_fc^T         [256][1344]
__device__ float g_woutT[EDD * EDD];   // w_out^T        [256][256]
__device__ float g_w[NBA * NW];        // fc logits      [1800][1344]
__device__ float g_fusedT[EDD * NBA];  // fused features^T [256][1800]

// =====================================================================
// Transpose: out[k][m] = in[m][k] (+ in2[m][k]).  in is [M][256].
// block (32,8), grid (256/32, ceil(M/32))
// =====================================================================
template<bool ADD2>
__global__ void __launch_bounds__(256) transpose_kernel(
    const float* __restrict__ in, const float* __restrict__ in2,
    float* __restrict__ out, int M)
{
    __shared__ float t[32][33];
    const int k0 = blockIdx.x * 32;
    const int m0 = blockIdx.y * 32;
    const int tx = threadIdx.x, ty = threadIdx.y;
#pragma unroll
    for (int j = ty; j < 32; j += 8) {
        int m = m0 + j;
        float v = 0.f;
        if (m < M) {
            v = in[(size_t)m * 256 + k0 + tx];
            if (ADD2) v += in2[(size_t)m * 256 + k0 + tx];
        }
        t[j][tx] = v;
    }
    __syncthreads();
#pragma unroll
    for (int j = ty; j < 32; j += 8) {
        int m = m0 + tx;
        if (m < M) out[(size_t)(k0 + j) * M + m] = t[tx][j];
    }
}

// =====================================================================
// SGEMM-TN: C[M][N] = AT^T @ BT + bias, K=256.
// AT [256][M], BT [256][N] both k-major (pre-transposed).
// 128x64 tile, 128 threads, 8x8 micro-tile. No smem transpose.
// =====================================================================
__global__ void __launch_bounds__(128) sgemm_tn(
    const float* __restrict__ AT, const float* __restrict__ BT,
    const float* __restrict__ bias, float* __restrict__ C,
    int M, int N)
{
    __shared__ float As[32][128];
    __shared__ float Bs[32][64];
    const int bm0 = blockIdx.y * 128;
    const int bn0 = blockIdx.x * 64;
    const int tid  = threadIdx.x;
    const int w    = tid >> 5;
    const int lane = tid & 31;
    const int ry   = lane >> 3;          // 0..3
    const int rx   = lane & 7;           // 0..7
    const int m0   = w * 32 + ry * 8;    // row offset in tile
    const int n0   = rx * 8;             // col offset in tile

    float acc[8][8];
#pragma unroll
    for (int i = 0; i < 8; i++)
#pragma unroll
        for (int j = 0; j < 8; j++) acc[i][j] = 0.f;

    for (int kt = 0; kt < 256; kt += 32) {
        // ---- stage A tile: 128x32 floats, coalesced, STS.128 conflict-free
#pragma unroll
        for (int s = 0; s < 8; s++) {
            int id = tid + s * 128;
            int k = id >> 5, mq = id & 31;
            int m = bm0 + mq * 4;
            float4 v = make_float4(0.f, 0.f, 0.f, 0.f);
            if (m < M) v = *(const float4*)(AT + (size_t)(kt + k) * M + m);
            *(float4*)&As[k][mq * 4] = v;
        }
        // ---- stage B tile: 64x32 floats (N multiples of 64 -> no guard)
#pragma unroll
        for (int s = 0; s < 4; s++) {
            int id = tid + s * 128;
            int k = id >> 4, nq = id & 15;
            *(float4*)&Bs[k][nq * 4] =
                *(const float4*)(BT + (size_t)(kt + k) * N + bn0 + nq * 4);
        }
        __syncthreads();

#pragma unroll
        for (int k = 0; k < 32; k++) {
            float4 a0 = *(const float4*)&As[k][m0];
            float4 a1 = *(const float4*)&As[k][m0 + 4];
            float4 b0 = *(const float4*)&Bs[k][n0];
            float4 b1 = *(const float4*)&Bs[k][n0 + 4];
            float am[8] = {a0.x, a0.y, a0.z, a0.w, a1.x, a1.y, a1.z, a1.w};
            float bv[8] = {b0.x, b0.y, b0.z, b0.w, b1.x, b1.y, b1.z, b1.w};
#pragma unroll
            for (int i = 0; i < 8; i++)
#pragma unroll
                for (int j = 0; j < 8; j++)
                    acc[i][j] = fmaf(am[i], bv[j], acc[i][j]);
        }
        __syncthreads();
    }

    float4 bb0 = *(const float4*)(bias + bn0 + n0);
    float4 bb1 = *(const float4*)(bias + bn0 + n0 + 4);
    float bv[8] = {bb0.x, bb0.y, bb0.z, bb0.w, bb1.x, bb1.y, bb1.z, bb1.w};
#pragma unroll
    for (int i = 0; i < 8; i++) {
        int m = bm0 + m0 + i;
        if (m >= M) continue;
        float4 o0, o1;
        o0.x = acc[i][0] + bv[0]; o0.y = acc[i][1] + bv[1];
        o0.z = acc[i][2] + bv[2]; o0.w = acc[i][3] + bv[3];
        o1.x = acc[i][4] + bv[4]; o1.y = acc[i][5] + bv[5];
        o1.z = acc[i][6] + bv[6]; o1.w = acc[i][7] + bv[7];
        *(float4*)(C + (size_t)m * N + bn0 + n0)     = o0;
        *(float4*)(C + (size_t)m * N + bn0 + n0 + 4) = o1;
    }
}

// =====================================================================
// Fused aggregation: softmax + keypoint projection + descriptor
// precompute + valid-sample compaction + gather/fuse.
// One block per anchor, 256 threads (one channel each).
// Writes fused features TRANSPOSED: g_fusedT[c][ba].
// =====================================================================
__global__ void __launch_bounds__(256) agg_kernel(
    const float* __restrict__ f0, const float* __restrict__ f1,
    const float* __restrict__ f2, const float* __restrict__ f3,
    const float* __restrict__ anchor, const float* __restrict__ proj,
    const float* __restrict__ wh)
{
    __shared__ float  s_w[NW];
    __shared__ float  s_uv[NCAM * NPT][2];
    __shared__ int    s_foff[NDESC];
    __shared__ int    s_hw[NDESC];
    __shared__ int    s_dx[NDESC];
    __shared__ int    s_dyW[NDESC];
    __shared__ float4 s_wt[NDESC];
    __shared__ int    s_widx[NDESC];
    __shared__ int    s_list[NDESC];
    __shared__ int    s_wcnt[8];

    const int ba   = blockIdx.x;
    const int b    = ba / AA;
    const int tid  = threadIdx.x;
    const int c    = tid;
    const int wrp  = tid >> 5;
    const int lane = tid & 31;

    // ---- load raw logits ----
    for (int i = tid; i < NW; i += 256) s_w[i] = g_w[(size_t)ba * NW + i];

    // ---- projection of 42 (cam,pt) keypoints ----
    if (tid < NCAM * NPT) {
        const float fsx[7] = {0.f, 0.45f, -0.45f, 0.f, 0.f, 0.f, 0.f};
        const float fsy[7] = {0.f, 0.f, 0.f, 0.45f, -0.45f, 0.f, 0.f};
        const float fsz[7] = {0.f, 0.f, 0.f, 0.f, 0.f, 0.45f, -0.45f};
        int cam = tid / NPT, p = tid % NPT;
        const float* an = anchor + (size_t)ba * 8;
        float e0 = expf(an[3]), e1 = expf(an[4]), e2 = expf(an[5]);
        float k0 = fsx[p] * e0, k1 = fsy[p] * e1, k2 = fsz[p] * e2;
        float sn = an[6], cs = an[7];
        float X = cs * k0 - sn * k1 + an[0];
        float Y = sn * k0 + cs * k1 + an[1];
        float Z = k2 + an[2];
        const float* M = proj + (size_t)(b * NCAM + cam) * 16;
        float d0 = M[0] * X + M[1] * Y + M[2]  * Z + M[3];
        float d1 = M[4] * X + M[5] * Y + M[6]  * Z + M[7];
        float d2 = M[8] * X + M[9] * Y + M[10] * Z + M[11];
        float iz = 1.f / fmaxf(d2, 1e-5f);
        float x = d0 * iz / fmaxf(wh[(size_t)(b * NCAM + cam) * 2 + 0], 1e-5f);
        float y = d1 * iz / fmaxf(wh[(size_t)(b * NCAM + cam) * 2 + 1], 1e-5f);
        s_uv[tid][0] = x * 2.f - 1.f;
        s_uv[tid][1] = y * 2.f - 1.f;
    }
    __syncthreads();

    // ---- softmax over 168 entries for group = warp id ----
    {
        float mx = -INFINITY;
        for (int cc = lane; cc < 168; cc += 32) mx = fmaxf(mx, s_w[cc * 8 + wrp]);
#pragma unroll
        for (int o = 16; o; o >>= 1) mx = fmaxf(mx, __shfl_xor_sync(0xffffffffu, mx, o));
        float sum = 0.f;
        for (int cc = lane; cc < 168; cc += 32) {
            float e = expf(s_w[cc * 8 + wrp] - mx);
            s_w[cc * 8 + wrp] = e;
            sum += e;
        }
#pragma unroll
        for (int o = 16; o; o >>= 1) sum += __shfl_xor_sync(0xffffffffu, sum, o);
        float inv = 1.f / sum;
        for (int cc = lane; cc < 168; cc += 32) s_w[cc * 8 + wrp] *= inv;
    }

    // ---- descriptor precompute for 168 (cam,pt,lvl) samples ----
    const int Hl[4]  = {64, 32, 16, 8};
    const int Wl[4]  = {176, 88, 44, 22};
    const int HWl[4] = {11264, 2816, 704, 176};
    int flag = 0;
    if (tid < NDESC) {
        int d = tid;
        int cam = d / (NPT * NLVL);
        int r   = d - cam * (NPT * NLVL);
        int p   = r >> 2;
        int lvl = r & 3;
        float u = s_uv[cam * NPT + p][0];
        float v = s_uv[cam * NPT + p][1];
        const int H = Hl[lvl], W = Wl[lvl];
        float gx = (u + 1.f) * (W * 0.5f) - 0.5f;
        float gy = (v + 1.f) * (H * 0.5f) - 0.5f;
        float x0f = floorf(gx), y0f = floorf(gy);
        float wx1 = gx - x0f, wy1 = gy - y0f;
        bool vx0 = (x0f >= 0.f)       && (x0f <= (float)(W - 1));
        bool vx1 = (x0f + 1.f >= 0.f) && (x0f + 1.f <= (float)(W - 1));
        bool vy0 = (y0f >= 0.f)       && (y0f <= (float)(H - 1));
        bool vy1 = (y0f + 1.f >= 0.f) && (y0f + 1.f <= (float)(H - 1));
        flag = ((vx0 || vx1) && (vy0 || vy1)) ? 1 : 0;
        int x0 = (int)fminf(fmaxf(x0f, 0.f),       (float)(W - 1));
        int x1 = (int)fminf(fmaxf(x0f + 1.f, 0.f), (float)(W - 1));
        int y0 = (int)fminf(fmaxf(y0f, 0.f),       (float)(H - 1));
        int y1 = (int)fminf(fmaxf(y0f + 1.f, 0.f), (float)(H - 1));
        s_foff[d] = (b * NCAM + cam) * EDD * HWl[lvl] + y0 * W + x0;
        s_hw[d]   = HWl[lvl];
        s_dx[d]   = x1 - x0;
        s_dyW[d]  = (y1 - y0) * W;
        float4 wt;
        wt.x = (vx0 && vy0) ? (1.f - wx1) * (1.f - wy1) : 0.f;
        wt.y = (vx1 && vy0) ? wx1 * (1.f - wy1)         : 0.f;
        wt.z = (vx0 && vy1) ? (1.f - wx1) * wy1         : 0.f;
        wt.w = (vx1 && vy1) ? wx1 * wy1                 : 0.f;
        s_wt[d]   = wt;
        s_widx[d] = ((cam * NLVL + lvl) * NPT + p) * NGRP;
    }

    // ---- deterministic compaction of valid descriptors ----
    unsigned bal = 0;
    if (wrp < 6) {
        bal = __ballot_sync(0xffffffffu, flag);
        if (lane == 0) s_wcnt[wrp] = __popc(bal);
    } else {
        if (lane == 0) s_wcnt[wrp] = 0;
    }
    __syncthreads();
    if (wrp < 6 && flag) {
        int base = 0;
        for (int w2 = 0; w2 < wrp; w2++) base += s_wcnt[w2];
        int pos = base + __popc(bal & ((1u << lane) - 1u));
        s_list[pos] = tid;
    }
    __syncthreads();
    int cnt = s_wcnt[0] + s_wcnt[1] + s_wcnt[2] + s_wcnt[3] + s_wcnt[4] + s_wcnt[5];

    // ---- gather + fuse over valid samples only ----
    const int g = wrp;
    float acc = 0.f;
#pragma unroll 2
    for (int i = 0; i < cnt; i++) {
        int d   = s_list[i];
        int lvl = d & 3;
        const float* fp = (lvl == 0) ? f0 : (lvl == 1) ? f1 : (lvl == 2) ? f2 : f3;
        const float* basep = fp + (size_t)(s_foff[d] + c * s_hw[d]);
        int dx = s_dx[d], dyW = s_dyW[d];
        float4 wt = s_wt[d];
        float v00 = basep[0];
        float v01 = basep[dx];
        float v10 = basep[dyW];
        float v11 = basep[dyW + dx];
        float s = fmaf(wt.x, v00, fmaf(wt.y, v01, fmaf(wt.z, v10, wt.w * v11)));
        acc = fmaf(s, s_w[s_widx[d] + g], acc);
    }
    // transposed store for the TN out-projection
    g_fusedT[(size_t)c * NBA + ba] = acc;
}

// =====================================================================
// launch
// =====================================================================
extern "C" void kernel_launch(void* const* d_in, const int* in_sizes, int n_in,
                              void* d_out, int out_size)
{
    const float* inst   = (const float*)d_in[0];
    const float* anchor = (const float*)d_in[1];
    const float* emb    = (const float*)d_in[2];
    const float* f0     = (const float*)d_in[3];
    const float* f1     = (const float*)d_in[4];
    const float* f2     = (const float*)d_in[5];
    const float* f3     = (const float*)d_in[6];
    const float* proj   = (const float*)d_in[7];
    const float* wh     = (const float*)d_in[8];
    const float* w_fc   = (const float*)d_in[9];
    const float* b_fc   = (const float*)d_in[10];
    const float* w_out  = (const float*)d_in[11];
    const float* b_out  = (const float*)d_in[12];
    float* out = (float*)d_out;

    float *featT, *wfcT, *woutT, *gw, *fusedT;
    cudaGetSymbolAddress((void**)&featT,  g_featT);
    cudaGetSymbolAddress((void**)&wfcT,   g_wfcT);
    cudaGetSymbolAddress((void**)&woutT,  g_woutT);
    cudaGetSymbolAddress((void**)&gw,     g_w);
    cudaGetSymbolAddress((void**)&fusedT, g_fusedT);

    dim3 tb(32, 8);
    // featT = (inst + emb)^T
    transpose_kernel<true><<<dim3(8, (NBA + 31) / 32), tb>>>(inst, emb, featT, NBA);
    // w_fc^T, w_out^T
    transpose_kernel<false><<<dim3(8, NW / 32),  tb>>>(w_fc,  (const float*)0, wfcT,  NW);
    transpose_kernel<false><<<dim3(8, EDD / 32), tb>>>(w_out, (const float*)0, woutT, EDD);

    // FC: g_w = featT^T @ wfcT + b_fc   [1800][1344]
    sgemm_tn<<<dim3(NW / 64, (NBA + 127) / 128), 128>>>(featT, wfcT, b_fc, gw, NBA, NW);

    // fused softmax + projection + sampling + fusion
    agg_kernel<<<NBA, 256>>>(f0, f1, f2, f3, anchor, proj, wh);

    // out-projection: out = fusedT^T @ woutT + b_out  [1800][256]
    sgemm_tn<<<dim3(EDD / 64, (NBA + 127) / 128), 128>>>(fusedT, woutT, b_out, out, NBA, EDD);
}